// round 13
// baseline (speedup 1.0000x reference)
#include <cuda_runtime.h>
#include <math.h>

#define TSTEPS 512
#define BATCH  64
#define DIN    256
#define HID    512
#define DOUT   256
#define G4H    2048
#define NBLK   128
#define NGE    20    // extra blocks in encoder recur kernel running dec-proj tiles
#define NCH    4     // batch chains
#define BCH    16    // batches per chain

typedef unsigned long long ull;

// ---------------- scratch ----------------
__device__ float d_Genc[(size_t)TSTEPS * G4H * BATCH];    // [t][gate*512+u][b]
__device__ float d_Gdec[(size_t)TSTEPS * G4H * BATCH];
__device__ float d_hq[NCH][2][256 * BCH * 2];             // [chain][parity][kpair][b16][2]
__device__ float d_cbuf[HID * BATCH];                     // [u][b]
__device__ float d_hs[(size_t)TSTEPS * HID * BATCH];      // [t][u][b]
__device__ float d_logits[(size_t)TSTEPS * BATCH * DOUT]; // [t][b][n]
__device__ unsigned d_cntg[NCH * 8 * 32];                 // group counters (stride-32)
__device__ unsigned d_cntr[NCH * 32];                     // root counters
__device__ volatile int d_epoch[NCH * 32];                // broadcast line per chain

// ---------------- helpers ----------------
__device__ __forceinline__ void fma2(ull& a, ull x, ull y) {
    asm("fma.rn.f32x2 %0, %1, %2, %3;" : "=l"(a) : "l"(x), "l"(y), "l"(a));
}
__device__ __forceinline__ void fadd2(ull& a, ull x) {
    asm("add.rn.f32x2 %0, %1, %2;" : "=l"(a) : "l"(a), "l"(x));
}
__device__ __forceinline__ ull pack2(float lo, float hi) {
    ull r; asm("mov.b64 %0, {%1, %2};" : "=l"(r) : "f"(lo), "f"(hi)); return r;
}
__device__ __forceinline__ float sum2(ull v) {
    float lo, hi; asm("mov.b64 {%0, %1}, %2;" : "=f"(lo), "=f"(hi) : "l"(v));
    return lo + hi;
}
__device__ __forceinline__ ull ldcg64(const ull* p) {
    ull v; asm volatile("ld.global.cg.u64 %0, [%1];" : "=l"(v) : "l"(p)); return v;
}
__device__ __forceinline__ int ld_acq(const volatile int* p) {
    int v; asm volatile("ld.acquire.gpu.global.s32 %0, [%1];" : "=r"(v) : "l"(p) : "memory");
    return v;
}
__device__ __forceinline__ void st_rel(volatile int* p, int v) {
    asm volatile("st.release.gpu.global.s32 [%0], %1;" :: "l"(p), "r"(v) : "memory");
}
__device__ __forceinline__ void barx(int id) {
    asm volatile("bar.sync %0, 128;" :: "r"(id) : "memory");
}
__device__ __forceinline__ float fsig(float x) {
    return __fdividef(1.0f, 1.0f + __expf(-x));
}
__device__ __forceinline__ float ftanh(float x) {
    float e = __expf(2.0f * x);                 // inf-safe
    return 1.0f - __fdividef(2.0f, e + 1.0f);
}

// ---------------- init: pack initial h/c per chain, reset sync state ----------------
__global__ __launch_bounds__(256) void init_state(const float* __restrict__ h0,
                                                  const float* __restrict__ c0) {
    int i = blockIdx.x * blockDim.x + threadIdx.x;
    if (i < NCH * 8) d_cntg[i * 32] = 0u;
    if (i < NCH) { d_cntr[i * 32] = 0u; d_epoch[i * 32] = 0; }
    if (i >= HID * BATCH) return;
    int b = i >> 9;                 // h0 layout [1][B][H]
    int u = i & 511;
    int q = b >> 4, b16 = b & 15;
    d_hq[q][0][((u >> 1) * BCH + b16) * 2 + (u & 1)] = h0[i];
    d_cbuf[u * BATCH + b] = c0[i];
}

// ---------------- unified register-blocked GEMM (R9-proven) ----------------
__global__ __launch_bounds__(256, 2) void gemm_kernel(
    const float* __restrict__ X, const float* __restrict__ W,
    const float* __restrict__ bias, float* __restrict__ Out,
    int Ntot, int K, int kchunks, int dec_shift, int x_kb, int out_bn) {
    __shared__ ull Wt[16 * 130];
    __shared__ ull Xt[16 * 66];

    int t  = blockIdx.y;
    int n0 = blockIdx.x * 128;
    int tid = threadIdx.x;
    int tx = tid & 15, ty = tid >> 4;

    ull acc[8][4];
#pragma unroll
    for (int i = 0; i < 8; i++)
#pragma unroll
        for (int j = 0; j < 4; j++) acc[i][j] = 0ull;

    for (int ch = 0; ch < kchunks; ch++) {
        for (int idx = tid; idx < 2048; idx += 256) {
            int kk = idx & 15, n = idx >> 4;
            Wt[kk * 130 + n] = *(const ull*)(W + (size_t)(n0 + n) * K + ch * 32 + kk * 2);
        }
        if (x_kb) {
            for (int idx = tid; idx < 1024; idx += 256) {
                int b = idx & 63, kk = idx >> 6;
                int kg = ch * 32 + kk * 2;
                Xt[kk * 66 + b] = pack2(X[((size_t)t * K + kg) * 64 + b],
                                        X[((size_t)t * K + kg + 1) * 64 + b]);
            }
        } else {
            bool zero = (dec_shift && t == 0);
            int trow = t - dec_shift;
            for (int idx = tid; idx < 1024; idx += 256) {
                int kk = idx & 15, b = idx >> 4;
                Xt[kk * 66 + b] = zero ? 0ull
                    : *(const ull*)(X + ((size_t)trow * 64 + b) * K + ch * 32 + kk * 2);
            }
        }
        __syncthreads();
#pragma unroll
        for (int kk = 0; kk < 16; kk++) {
            ulonglong2 xv0 = *(const ulonglong2*)&Xt[kk * 66 + tx * 4];
            ulonglong2 xv1 = *(const ulonglong2*)&Xt[kk * 66 + tx * 4 + 2];
            ull xs0 = xv0.x, xs1 = xv0.y, xs2 = xv1.x, xs3 = xv1.y;
#pragma unroll
            for (int q = 0; q < 4; q++) {
                ulonglong2 wv = *(const ulonglong2*)&Wt[kk * 130 + ty * 8 + 2 * q];
                fma2(acc[2 * q][0], wv.x, xs0);
                fma2(acc[2 * q][1], wv.x, xs1);
                fma2(acc[2 * q][2], wv.x, xs2);
                fma2(acc[2 * q][3], wv.x, xs3);
                fma2(acc[2 * q + 1][0], wv.y, xs0);
                fma2(acc[2 * q + 1][1], wv.y, xs1);
                fma2(acc[2 * q + 1][2], wv.y, xs2);
                fma2(acc[2 * q + 1][3], wv.y, xs3);
            }
        }
        __syncthreads();
    }

    if (out_bn) {
        float bb[8];
#pragma unroll
        for (int i = 0; i < 8; i++) bb[i] = bias[n0 + ty * 8 + i];
#pragma unroll
        for (int j = 0; j < 4; j++) {
            int b = tx * 4 + j;
            float v[8];
#pragma unroll
            for (int i = 0; i < 8; i++) v[i] = sum2(acc[i][j]) + bb[i];
            float* op = Out + ((size_t)t * 64 + b) * Ntot + n0 + ty * 8;
            *(float4*)op       = make_float4(v[0], v[1], v[2], v[3]);
            *(float4*)(op + 4) = make_float4(v[4], v[5], v[6], v[7]);
        }
    } else {
#pragma unroll
        for (int i = 0; i < 8; i++) {
            int n = n0 + ty * 8 + i;
            float bb = bias[n];
            float4 o = make_float4(sum2(acc[i][0]) + bb, sum2(acc[i][1]) + bb,
                                   sum2(acc[i][2]) + bb, sum2(acc[i][3]) + bb);
            *(float4*)(Out + ((size_t)t * Ntot + n) * 64 + tx * 4) = o;
        }
    }
}

// ---------------- dec-proj tile (run by extra blocks inside encoder recur) ----------------
// One 128n x 64b tile of d_Gdec[t][n][b] = dec_in[t] @ dWih^T + db, dec_in[0]=0.
// 512 threads: thread -> 4n x 4b. Uses the block's dynamic smem.
__device__ __forceinline__ void dec_proj_tile(
        ull* Wt, ull* Xt, const float* __restrict__ X,
        const float* __restrict__ W, const float* __restrict__ bias, int tt) {
    int t  = tt >> 4;
    int n0 = (tt & 15) * 128;
    int tid = threadIdx.x;
    int tx = tid & 15, ty = tid >> 4;   // ty 0..31 -> 4 n's
    ull acc[4][4];
#pragma unroll
    for (int i = 0; i < 4; i++)
#pragma unroll
        for (int j = 0; j < 4; j++) acc[i][j] = 0ull;

    for (int ch = 0; ch < DOUT / 32; ch++) {
        for (int idx = tid; idx < 2048; idx += 512) {
            int kk = idx & 15, n = idx >> 4;
            Wt[kk * 130 + n] = *(const ull*)(W + (size_t)(n0 + n) * DOUT + ch * 32 + kk * 2);
        }
        if (t == 0) {
            for (int idx = tid; idx < 1024; idx += 512) {
                int kk = idx & 15, b = idx >> 4;
                Xt[kk * 66 + b] = 0ull;
            }
        } else {
            for (int idx = tid; idx < 1024; idx += 512) {
                int kk = idx & 15, b = idx >> 4;
                Xt[kk * 66 + b] =
                    *(const ull*)(X + ((size_t)(t - 1) * 64 + b) * DOUT + ch * 32 + kk * 2);
            }
        }
        __syncthreads();
#pragma unroll
        for (int kk = 0; kk < 16; kk++) {
            ulonglong2 xv0 = *(const ulonglong2*)&Xt[kk * 66 + tx * 4];
            ulonglong2 xv1 = *(const ulonglong2*)&Xt[kk * 66 + tx * 4 + 2];
            ulonglong2 wv0 = *(const ulonglong2*)&Wt[kk * 130 + ty * 4];
            ulonglong2 wv1 = *(const ulonglong2*)&Wt[kk * 130 + ty * 4 + 2];
            fma2(acc[0][0], wv0.x, xv0.x); fma2(acc[0][1], wv0.x, xv0.y);
            fma2(acc[0][2], wv0.x, xv1.x); fma2(acc[0][3], wv0.x, xv1.y);
            fma2(acc[1][0], wv0.y, xv0.x); fma2(acc[1][1], wv0.y, xv0.y);
            fma2(acc[1][2], wv0.y, xv1.x); fma2(acc[1][3], wv0.y, xv1.y);
            fma2(acc[2][0], wv1.x, xv0.x); fma2(acc[2][1], wv1.x, xv0.y);
            fma2(acc[2][2], wv1.x, xv1.x); fma2(acc[2][3], wv1.x, xv1.y);
            fma2(acc[3][0], wv1.y, xv0.x); fma2(acc[3][1], wv1.y, xv0.y);
            fma2(acc[3][2], wv1.y, xv1.x); fma2(acc[3][3], wv1.y, xv1.y);
        }
        __syncthreads();
    }
#pragma unroll
    for (int i = 0; i < 4; i++) {
        int n = n0 + ty * 4 + i;
        float bb = bias[n];
        float4 o = make_float4(sum2(acc[i][0]) + bb, sum2(acc[i][1]) + bb,
                               sum2(acc[i][2]) + bb, sum2(acc[i][3]) + bb);
        *(float4*)(d_Gdec + ((size_t)t * G4H + n) * 64 + tx * 4) = o;
    }
}

// ---------------- persistent recurrent LSTM: 4 chains, tree-atomic sync ----------------
// Blocks 0..127: recurrence (4 units each; chain q on warps 4q..4q+3).
// Blocks >=128 (encoder launch only): dec-proj GEMM tiles on otherwise-idle SMs.
// Arrival per chain per step: 2-level atomics (8 groups of 16 -> root -> epoch).
__global__ __launch_bounds__(512) void recur_kernel(const float* __restrict__ Whh,
                                                    int which, int sbase,
                                                    const float* __restrict__ Xd,
                                                    const float* __restrict__ Wd,
                                                    const float* __restrict__ bd) {
    extern __shared__ ull sm[];

    int bid = blockIdx.x;
    if (bid >= NBLK) {
        // ---- embedded dec-proj worker ----
        ull* Wt = sm;            // 2080 ull
        ull* Xt = sm + 2080;     // 1056 ull
        int nge = gridDim.x - NBLK;
        for (int tt = bid - NBLK; tt < TSTEPS * 16; tt += nge)
            dec_proj_tile(Wt, Xt, Xd, Wd, bd, tt);
        return;
    }

    ull* ws  = sm;            // [kpair][16 rows]   4096 ull = 32 KB
    ull* red = sm + 4096;     // per chain: [(row*16+b16)*9 + slot], 2304 ull each

    const float* __restrict__ G = which ? d_Gdec : d_Genc;
    int tid = threadIdx.x;
    int w = tid >> 5, l = tid & 31;
    int q = w >> 2;                 // chain
    int wi = w & 3;                 // warp-in-chain (also SMSP)
    int b16 = l & 15, kh = l >> 4;  // FMA lane mapping
    int u0 = bid * 4;

    // weights: [kpair][row], row = gate*4 + unit
    for (int idx = tid; idx < 4096; idx += 512) {
        int kp = idx >> 4, r = idx & 15;
        int g = r >> 2, uu = r & 3;
        ws[idx] = *(const ull*)(Whh + ((size_t)(g * HID + u0 + uu)) * HID + kp * 2);
    }
    __syncthreads();

    // epilogue mapping: warps wi<2, 64 threads -> (ul, eb16)
    int e = wi * 32 + l;
    int ul = (e >> 4) & 3, eb16 = e & 15;
    int u = u0 + ul;
    float c = (wi < 2) ? d_cbuf[u * BATCH + q * BCH + eb16] : 0.0f;

    ull* rq = red + q * 2304;
    int kbase = wi * 64 + kh * 32;
    const int barid = 1 + q;
    volatile int* epoch = &d_epoch[q * 32];
    unsigned* cg = &d_cntg[(q * 8 + (bid >> 4)) * 32];
    unsigned* cr = &d_cntr[q * 32];

    for (int t = 0; t < TSTEPS; t++) {
        int s = sbase + t;

        // prefetch this chain's precomputed gate inputs (LDGs overlap the wait)
        float pi = 0.f, pf = 0.f, pg = 0.f, po = 0.f;
        if (wi < 2) {
            size_t gb = ((size_t)t * G4H + u) * BATCH + q * BCH + eb16;
            pi = G[gb];
            pf = G[gb + (size_t)512 * 64];
            pg = G[gb + (size_t)1024 * 64];
            po = G[gb + (size_t)1536 * 64];
        }

        // wait for h_s (single poller per chain per block)
        if (wi == 0 && l == 0) { while (ld_acq(epoch) < s) { } }
        barx(barid);

        const ull* hsrc = (const ull*)d_hq[q][s & 1] + b16;
        ull acc[16];
#pragma unroll
        for (int r = 0; r < 16; r++) acc[r] = 0ull;

        ull hg[2][8];
#pragma unroll
        for (int j = 0; j < 8; j++) hg[0][j] = ldcg64(hsrc + (size_t)(kbase + j) * BCH);
#pragma unroll
        for (int g4 = 0; g4 < 4; g4++) {
            int cur = g4 & 1, nxt = cur ^ 1;
            if (g4 < 3) {
#pragma unroll
                for (int j = 0; j < 8; j++)
                    hg[nxt][j] = ldcg64(hsrc + (size_t)(kbase + (g4 + 1) * 8 + j) * BCH);
            }
#pragma unroll
            for (int j = 0; j < 8; j++) {
                const ulonglong2* wp = (const ulonglong2*)(ws + (size_t)(kbase + g4 * 8 + j) * 16);
                ull hv = hg[cur][j];
#pragma unroll
                for (int rp = 0; rp < 8; rp++) {
                    ulonglong2 wv = wp[rp];
                    fma2(acc[2 * rp],     wv.x, hv);
                    fma2(acc[2 * rp + 1], wv.y, hv);
                }
            }
        }
#pragma unroll
        for (int r = 0; r < 16; r++)
            rq[(size_t)(r * 16 + b16) * 9 + wi * 2 + kh] = acc[r];
        barx(barid);                        // partials ready; h_s reads done

        if (wi < 2) {
            float gate[4];
#pragma unroll
            for (int g = 0; g < 4; g++) {
                int r = g * 4 + ul;
                const ull* rp_ = rq + (size_t)(r * 16 + eb16) * 9;
                ull a0 = rp_[0]; fadd2(a0, rp_[1]); fadd2(a0, rp_[2]); fadd2(a0, rp_[3]);
                ull a1 = rp_[4]; fadd2(a1, rp_[5]); fadd2(a1, rp_[6]); fadd2(a1, rp_[7]);
                fadd2(a0, a1);
                gate[g] = sum2(a0);
            }
            float iv = fsig(gate[0] + pi);
            float fv = fsig(gate[1] + pf);
            float gv = ftanh(gate[2] + pg);
            float ov = fsig(gate[3] + po);
            c = fv * c + iv * gv;
            float h = ov * ftanh(c);

            d_hq[q][(s + 1) & 1][((u >> 1) * BCH + eb16) * 2 + (u & 1)] = h;
            if (which) d_hs[((size_t)t * HID + u) * BATCH + q * BCH + eb16] = h;
        }
        barx(barid);                        // h_{s+1} visible chain-wide

        // tree arrival: group counter (16 blocks) -> root (8 groups) -> epoch
        if (wi == 3 && l == 0) {
            __threadfence();
            unsigned og = atomicAdd(cg, 1u);
            if (og == 16u * (unsigned)(s + 1) - 1u) {
                unsigned orr = atomicAdd(cr, 1u);
                if (orr == 8u * (unsigned)(s + 1) - 1u) st_rel(epoch, s + 1);
            }
        }
    }
    if (wi < 2) d_cbuf[u * BATCH + q * BCH + eb16] = c;   // enc -> dec handoff
}

// ---------------- softmax over last dim (256), one warp per (t,b) row ----------------
__global__ __launch_bounds__(256) void softmax_kernel(float* __restrict__ out) {
    int row = blockIdx.x * 8 + (threadIdx.x >> 5);
    if (row >= TSTEPS * BATCH) return;
    int lane = threadIdx.x & 31;
    const float* lp = d_logits + (size_t)row * DOUT;
    float v[8];
    float m = -INFINITY;
#pragma unroll
    for (int i = 0; i < 8; i++) { v[i] = lp[lane + 32 * i]; m = fmaxf(m, v[i]); }
#pragma unroll
    for (int o = 16; o > 0; o >>= 1) m = fmaxf(m, __shfl_xor_sync(0xffffffffu, m, o));
    float s = 0.0f;
#pragma unroll
    for (int i = 0; i < 8; i++) { v[i] = expf(v[i] - m); s += v[i]; }
#pragma unroll
    for (int o = 16; o > 0; o >>= 1) s += __shfl_xor_sync(0xffffffffu, s, o);
    float inv = 1.0f / s;
    float* op = out + (size_t)row * DOUT;
#pragma unroll
    for (int i = 0; i < 8; i++) op[lane + 32 * i] = v[i] * inv;
}

// ---------------- launch ----------------
extern "C" void kernel_launch(void* const* d_in, const int* in_sizes, int n_in,
                              void* d_out, int out_size) {
    const float* x      = (const float*)d_in[0];
    const float* target = (const float*)d_in[1];
    const float* h0     = (const float*)d_in[2];
    const float* c0     = (const float*)d_in[3];
    const float* eWih   = (const float*)d_in[4];
    const float* eWhh   = (const float*)d_in[5];
    const float* eb     = (const float*)d_in[6];
    const float* dWih   = (const float*)d_in[7];
    const float* dWhh   = (const float*)d_in[8];
    const float* db     = (const float*)d_in[9];
    const float* fcW    = (const float*)d_in[10];
    const float* fcb    = (const float*)d_in[11];
    float* out = (float*)d_out;

    const int smem_recur = (4096 + NCH * 2304) * 8;   // 106496 B
    cudaFuncSetAttribute(recur_kernel, cudaFuncAttributeMaxDynamicSharedMemorySize, smem_recur);

    init_state<<<128, 256>>>(h0, c0);

    float* genc; cudaGetSymbolAddress((void**)&genc, d_Genc);
    float* ghs;  cudaGetSymbolAddress((void**)&ghs,  d_hs);
    float* glog; cudaGetSymbolAddress((void**)&glog, d_logits);

    // encoder input projection (decoder projection runs INSIDE the encoder
    // recurrence on the 20 spare SMs)
    gemm_kernel<<<dim3(16, TSTEPS), 256>>>(x, eWih, eb, genc, G4H, DIN, DIN / 32, 0, 0, 0);

    recur_kernel<<<NBLK + NGE, 512, smem_recur>>>(eWhh, 0, 0, target, dWih, db);
    recur_kernel<<<NBLK, 512, smem_recur>>>(dWhh, 1, TSTEPS, nullptr, nullptr, nullptr);

    gemm_kernel<<<dim3(2, TSTEPS), 256>>>(ghs, fcW, fcb, glog, DOUT, HID, HID / 32, 0, 1, 1);
    softmax_kernel<<<(TSTEPS * BATCH + 7) / 8, 256>>>(out);
}

// round 14
// speedup vs baseline: 1.9165x; 1.9165x over previous
#include <cuda_runtime.h>
#include <math.h>

#define TSTEPS 512
#define BATCH  64
#define DIN    256
#define HID    512
#define DOUT   256
#define G4H    2048
#define NBLK   128
#define NCH    4      // batch chains
#define BCH    16     // batches per chain

typedef unsigned long long ull;

// ---------------- scratch ----------------
__device__ float d_Genc[(size_t)TSTEPS * G4H * BATCH];    // [t][gate*512+u][b]
__device__ float d_Gdec[(size_t)TSTEPS * G4H * BATCH];
__device__ float d_hq[NCH][2][256 * BCH * 2];             // [chain][parity][kpair][b16][2]
__device__ float d_cbuf[HID * BATCH];                     // [u][b]
__device__ float d_hs[(size_t)TSTEPS * HID * BATCH];      // [t][u][b]
__device__ float d_logits[(size_t)TSTEPS * BATCH * DOUT]; // [t][b][n]
__device__ unsigned d_cntg[NCH * 8 * 32];                 // group counters (stride-32 lines)
__device__ unsigned d_cntr[NCH * 32];                     // root counters
__device__ volatile int d_epoch[NCH * 32];                // broadcast line per chain

// ---------------- helpers ----------------
__device__ __forceinline__ void fma2(ull& a, ull x, ull y) {
    asm("fma.rn.f32x2 %0, %1, %2, %3;" : "=l"(a) : "l"(x), "l"(y), "l"(a));
}
__device__ __forceinline__ void fadd2(ull& a, ull x) {
    asm("add.rn.f32x2 %0, %1, %2;" : "=l"(a) : "l"(a), "l"(x));
}
__device__ __forceinline__ ull pack2(float lo, float hi) {
    ull r; asm("mov.b64 %0, {%1, %2};" : "=l"(r) : "f"(lo), "f"(hi)); return r;
}
__device__ __forceinline__ float sum2(ull v) {
    float lo, hi; asm("mov.b64 {%0, %1}, %2;" : "=f"(lo), "=f"(hi) : "l"(v));
    return lo + hi;
}
__device__ __forceinline__ ull ldcg64(const ull* p) {
    ull v; asm volatile("ld.global.cg.u64 %0, [%1];" : "=l"(v) : "l"(p)); return v;
}
__device__ __forceinline__ int ld_acq(const volatile int* p) {
    int v; asm volatile("ld.acquire.gpu.global.s32 %0, [%1];" : "=r"(v) : "l"(p) : "memory");
    return v;
}
__device__ __forceinline__ void st_rel(volatile int* p, int v) {
    asm volatile("st.release.gpu.global.s32 [%0], %1;" :: "l"(p), "r"(v) : "memory");
}
__device__ __forceinline__ void barx(int id) {
    asm volatile("bar.sync %0, 128;" :: "r"(id) : "memory");
}
__device__ __forceinline__ float fsig(float x) {
    return __fdividef(1.0f, 1.0f + __expf(-x));
}
__device__ __forceinline__ float ftanh(float x) {
    float e = __expf(2.0f * x);                 // inf-safe
    return 1.0f - __fdividef(2.0f, e + 1.0f);
}

// ---------------- init: pack initial h/c per chain, reset sync state ----------------
__global__ __launch_bounds__(256) void init_state(const float* __restrict__ h0,
                                                  const float* __restrict__ c0) {
    int i = blockIdx.x * blockDim.x + threadIdx.x;
    if (i < NCH * 8) d_cntg[i * 32] = 0u;
    if (i < NCH) { d_cntr[i * 32] = 0u; d_epoch[i * 32] = 0; }
    if (i >= HID * BATCH) return;
    int b = i >> 9;                 // h0 layout [1][B][H]
    int u = i & 511;
    int q = b >> 4, b16 = b & 15;
    d_hq[q][0][((u >> 1) * BCH + b16) * 2 + (u & 1)] = h0[i];
    d_cbuf[u * BATCH + b] = c0[i];
}

// ---------------- unified register-blocked GEMM (R9-proven) ----------------
__global__ __launch_bounds__(256, 2) void gemm_kernel(
    const float* __restrict__ X, const float* __restrict__ W,
    const float* __restrict__ bias, float* __restrict__ Out,
    int Ntot, int K, int kchunks, int dec_shift, int x_kb, int out_bn) {
    __shared__ ull Wt[16 * 130];
    __shared__ ull Xt[16 * 66];

    int t  = blockIdx.y;
    int n0 = blockIdx.x * 128;
    int tid = threadIdx.x;
    int tx = tid & 15, ty = tid >> 4;

    ull acc[8][4];
#pragma unroll
    for (int i = 0; i < 8; i++)
#pragma unroll
        for (int j = 0; j < 4; j++) acc[i][j] = 0ull;

    for (int ch = 0; ch < kchunks; ch++) {
        for (int idx = tid; idx < 2048; idx += 256) {
            int kk = idx & 15, n = idx >> 4;
            Wt[kk * 130 + n] = *(const ull*)(W + (size_t)(n0 + n) * K + ch * 32 + kk * 2);
        }
        if (x_kb) {
            for (int idx = tid; idx < 1024; idx += 256) {
                int b = idx & 63, kk = idx >> 6;
                int kg = ch * 32 + kk * 2;
                Xt[kk * 66 + b] = pack2(X[((size_t)t * K + kg) * 64 + b],
                                        X[((size_t)t * K + kg + 1) * 64 + b]);
            }
        } else {
            bool zero = (dec_shift && t == 0);
            int trow = t - dec_shift;
            for (int idx = tid; idx < 1024; idx += 256) {
                int kk = idx & 15, b = idx >> 4;
                Xt[kk * 66 + b] = zero ? 0ull
                    : *(const ull*)(X + ((size_t)trow * 64 + b) * K + ch * 32 + kk * 2);
            }
        }
        __syncthreads();
#pragma unroll
        for (int kk = 0; kk < 16; kk++) {
            ulonglong2 xv0 = *(const ulonglong2*)&Xt[kk * 66 + tx * 4];
            ulonglong2 xv1 = *(const ulonglong2*)&Xt[kk * 66 + tx * 4 + 2];
            ull xs0 = xv0.x, xs1 = xv0.y, xs2 = xv1.x, xs3 = xv1.y;
#pragma unroll
            for (int q = 0; q < 4; q++) {
                ulonglong2 wv = *(const ulonglong2*)&Wt[kk * 130 + ty * 8 + 2 * q];
                fma2(acc[2 * q][0], wv.x, xs0);
                fma2(acc[2 * q][1], wv.x, xs1);
                fma2(acc[2 * q][2], wv.x, xs2);
                fma2(acc[2 * q][3], wv.x, xs3);
                fma2(acc[2 * q + 1][0], wv.y, xs0);
                fma2(acc[2 * q + 1][1], wv.y, xs1);
                fma2(acc[2 * q + 1][2], wv.y, xs2);
                fma2(acc[2 * q + 1][3], wv.y, xs3);
            }
        }
        __syncthreads();
    }

    if (out_bn) {
        float bb[8];
#pragma unroll
        for (int i = 0; i < 8; i++) bb[i] = bias[n0 + ty * 8 + i];
#pragma unroll
        for (int j = 0; j < 4; j++) {
            int b = tx * 4 + j;
            float v[8];
#pragma unroll
            for (int i = 0; i < 8; i++) v[i] = sum2(acc[i][j]) + bb[i];
            float* op = Out + ((size_t)t * 64 + b) * Ntot + n0 + ty * 8;
            *(float4*)op       = make_float4(v[0], v[1], v[2], v[3]);
            *(float4*)(op + 4) = make_float4(v[4], v[5], v[6], v[7]);
        }
    } else {
#pragma unroll
        for (int i = 0; i < 8; i++) {
            int n = n0 + ty * 8 + i;
            float bb = bias[n];
            float4 o = make_float4(sum2(acc[i][0]) + bb, sum2(acc[i][1]) + bb,
                                   sum2(acc[i][2]) + bb, sum2(acc[i][3]) + bb);
            *(float4*)(Out + ((size_t)t * Ntot + n) * 64 + tx * 4) = o;
        }
    }
}

// ---------------- persistent recurrent LSTM: 4 chains, tree-atomic arrival ----------------
// Exactly the R9 kernel (best measured) with ONE change: the 128-deep
// same-address atomic arrival chain is replaced by a 2-level tree
// (8 group counters of 16 arrivals -> root of 8 -> epoch broadcast line).
__global__ __launch_bounds__(512) void recur_kernel(const float* __restrict__ Whh,
                                                    int which, int sbase) {
    extern __shared__ ull sm[];
    ull* ws  = sm;            // [kpair][16 rows]   4096 ull = 32 KB
    ull* red = sm + 4096;     // per chain: [(row*16+b16)*9 + slot], 2304 ull each

    const float* __restrict__ G = which ? d_Gdec : d_Genc;
    int tid = threadIdx.x;
    int w = tid >> 5, l = tid & 31;
    int q = w >> 2;                 // chain
    int wi = w & 3;                 // warp-in-chain (also SMSP)
    int b16 = l & 15, kh = l >> 4;  // FMA lane mapping
    int u0 = blockIdx.x * 4;
    int bid = blockIdx.x;

    // weights: [kpair][row], row = gate*4 + unit
    for (int idx = tid; idx < 4096; idx += 512) {
        int kp = idx >> 4, r = idx & 15;
        int g = r >> 2, uu = r & 3;
        ws[idx] = *(const ull*)(Whh + ((size_t)(g * HID + u0 + uu)) * HID + kp * 2);
    }
    __syncthreads();

    // epilogue mapping: warps wi<2, 64 threads -> (ul, eb16)
    int e = wi * 32 + l;
    int ul = (e >> 4) & 3, eb16 = e & 15;
    int u = u0 + ul;
    float c = (wi < 2) ? d_cbuf[u * BATCH + q * BCH + eb16] : 0.0f;

    ull* rq = red + q * 2304;
    int kbase = wi * 64 + kh * 32;
    const int barid = 1 + q;
    volatile int* epoch = &d_epoch[q * 32];
    unsigned* cg = &d_cntg[(q * 8 + (bid >> 4)) * 32];
    unsigned* cr = &d_cntr[q * 32];

    for (int t = 0; t < TSTEPS; t++) {
        int s = sbase + t;

        // prefetch this chain's precomputed gate inputs (LDGs overlap the wait)
        float pi = 0.f, pf = 0.f, pg = 0.f, po = 0.f;
        if (wi < 2) {
            size_t gb = ((size_t)t * G4H + u) * BATCH + q * BCH + eb16;
            pi = G[gb];
            pf = G[gb + (size_t)512 * 64];
            pg = G[gb + (size_t)1024 * 64];
            po = G[gb + (size_t)1536 * 64];
        }

        // wait for h_s (single poller per chain per block)
        if (wi == 0 && l == 0) { while (ld_acq(epoch) < s) { } }
        barx(barid);

        const ull* hsrc = (const ull*)d_hq[q][s & 1] + b16;
        ull acc[16];
#pragma unroll
        for (int r = 0; r < 16; r++) acc[r] = 0ull;

        ull hg[2][8];
#pragma unroll
        for (int j = 0; j < 8; j++) hg[0][j] = ldcg64(hsrc + (size_t)(kbase + j) * BCH);
#pragma unroll
        for (int g4 = 0; g4 < 4; g4++) {
            int cur = g4 & 1, nxt = cur ^ 1;
            if (g4 < 3) {
#pragma unroll
                for (int j = 0; j < 8; j++)
                    hg[nxt][j] = ldcg64(hsrc + (size_t)(kbase + (g4 + 1) * 8 + j) * BCH);
            }
#pragma unroll
            for (int j = 0; j < 8; j++) {
                const ulonglong2* wp = (const ulonglong2*)(ws + (size_t)(kbase + g4 * 8 + j) * 16);
                ull hv = hg[cur][j];
#pragma unroll
                for (int rp = 0; rp < 8; rp++) {
                    ulonglong2 wv = wp[rp];
                    fma2(acc[2 * rp],     wv.x, hv);
                    fma2(acc[2 * rp + 1], wv.y, hv);
                }
            }
        }
#pragma unroll
        for (int r = 0; r < 16; r++)
            rq[(size_t)(r * 16 + b16) * 9 + wi * 2 + kh] = acc[r];
        barx(barid);                        // partials ready; h_s reads done

        if (wi < 2) {
            float gate[4];
#pragma unroll
            for (int g = 0; g < 4; g++) {
                int r = g * 4 + ul;
                const ull* rp_ = rq + (size_t)(r * 16 + eb16) * 9;
                ull a0 = rp_[0]; fadd2(a0, rp_[1]); fadd2(a0, rp_[2]); fadd2(a0, rp_[3]);
                ull a1 = rp_[4]; fadd2(a1, rp_[5]); fadd2(a1, rp_[6]); fadd2(a1, rp_[7]);
                fadd2(a0, a1);
                gate[g] = sum2(a0);
            }
            float iv = fsig(gate[0] + pi);
            float fv = fsig(gate[1] + pf);
            float gv = ftanh(gate[2] + pg);
            float ov = fsig(gate[3] + po);
            c = fv * c + iv * gv;
            float h = ov * ftanh(c);

            d_hq[q][(s + 1) & 1][((u >> 1) * BCH + eb16) * 2 + (u & 1)] = h;
            if (which) d_hs[((size_t)t * HID + u) * BATCH + q * BCH + eb16] = h;
        }
        barx(barid);                        // h_{s+1} visible chain-wide

        // tree arrival: group counter (16 blocks) -> root (8 groups) -> epoch
        if (wi == 3 && l == 0) {
            __threadfence();
            unsigned og = atomicAdd(cg, 1u);
            if (og == 16u * (unsigned)(s + 1) - 1u) {
                unsigned orr = atomicAdd(cr, 1u);
                if (orr == 8u * (unsigned)(s + 1) - 1u) st_rel(epoch, s + 1);
            }
        }
    }
    if (wi < 2) d_cbuf[u * BATCH + q * BCH + eb16] = c;   // enc -> dec handoff
}

// ---------------- softmax over last dim (256), one warp per (t,b) row ----------------
__global__ __launch_bounds__(256) void softmax_kernel(float* __restrict__ out) {
    int row = blockIdx.x * 8 + (threadIdx.x >> 5);
    if (row >= TSTEPS * BATCH) return;
    int lane = threadIdx.x & 31;
    const float* lp = d_logits + (size_t)row * DOUT;
    float v[8];
    float m = -INFINITY;
#pragma unroll
    for (int i = 0; i < 8; i++) { v[i] = lp[lane + 32 * i]; m = fmaxf(m, v[i]); }
#pragma unroll
    for (int o = 16; o > 0; o >>= 1) m = fmaxf(m, __shfl_xor_sync(0xffffffffu, m, o));
    float s = 0.0f;
#pragma unroll
    for (int i = 0; i < 8; i++) { v[i] = expf(v[i] - m); s += v[i]; }
#pragma unroll
    for (int o = 16; o > 0; o >>= 1) s += __shfl_xor_sync(0xffffffffu, s, o);
    float inv = 1.0f / s;
    float* op = out + (size_t)row * DOUT;
#pragma unroll
    for (int i = 0; i < 8; i++) op[lane + 32 * i] = v[i] * inv;
}

// ---------------- launch ----------------
extern "C" void kernel_launch(void* const* d_in, const int* in_sizes, int n_in,
                              void* d_out, int out_size) {
    const float* x      = (const float*)d_in[0];
    const float* target = (const float*)d_in[1];
    const float* h0     = (const float*)d_in[2];
    const float* c0     = (const float*)d_in[3];
    const float* eWih   = (const float*)d_in[4];
    const float* eWhh   = (const float*)d_in[5];
    const float* eb     = (const float*)d_in[6];
    const float* dWih   = (const float*)d_in[7];
    const float* dWhh   = (const float*)d_in[8];
    const float* db     = (const float*)d_in[9];
    const float* fcW    = (const float*)d_in[10];
    const float* fcb    = (const float*)d_in[11];
    float* out = (float*)d_out;

    const int smem_recur = (4096 + NCH * 2304) * 8;   // 106496 B
    cudaFuncSetAttribute(recur_kernel, cudaFuncAttributeMaxDynamicSharedMemorySize, smem_recur);

    init_state<<<128, 256>>>(h0, c0);

    float* genc; cudaGetSymbolAddress((void**)&genc, d_Genc);
    float* gdec; cudaGetSymbolAddress((void**)&gdec, d_Gdec);
    float* ghs;  cudaGetSymbolAddress((void**)&ghs,  d_hs);
    float* glog; cudaGetSymbolAddress((void**)&glog, d_logits);

    gemm_kernel<<<dim3(16, TSTEPS), 256>>>(x,      eWih, eb, genc, G4H, DIN, DIN / 32, 0, 0, 0);
    gemm_kernel<<<dim3(16, TSTEPS), 256>>>(target, dWih, db, gdec, G4H, DOUT, DOUT / 32, 1, 0, 0);

    recur_kernel<<<NBLK, 512, smem_recur>>>(eWhh, 0, 0);
    recur_kernel<<<NBLK, 512, smem_recur>>>(dWhh, 1, TSTEPS);

    gemm_kernel<<<dim3(2, TSTEPS), 256>>>(ghs, fcW, fcb, glog, DOUT, HID, HID / 32, 0, 1, 1);
    softmax_kernel<<<(TSTEPS * BATCH + 7) / 8, 256>>>(out);
}